// round 2
// baseline (speedup 1.0000x reference)
#include <cuda_runtime.h>
#include <cstdint>

#define D         64
#define EDGE_DIM  16
#define MSG_IN    144
#define UPD_IN    128
#define MAXN      50000
#define MAXE      800000

// ---------------- scratch (device globals; no allocation allowed) ----------------
__device__ __align__(256) float g_x[MAXN * D];
__device__ __align__(256) float g_P[MAXN * D];
__device__ __align__(256) float g_Q[MAXN * D];
__device__ __align__(256) float g_agg[MAXN * D];
__device__ int g_src[MAXE];
__device__ int g_dst[MAXE];
__device__ int g_is64;

typedef unsigned long long u64;

// ---------------- packed f32x2 helpers ----------------
__device__ __forceinline__ u64 pack2(float lo, float hi) {
    u64 r; asm("mov.b64 %0, {%1,%2};" : "=l"(r) : "f"(lo), "f"(hi)); return r;
}
__device__ __forceinline__ void fma2(u64& acc, u64 a, u64 b) {
    asm("fma.rn.f32x2 %0, %1, %2, %0;" : "+l"(acc) : "l"(a), "l"(b));
}
__device__ __forceinline__ u64 add2(u64 a, u64 b) {
    u64 r; asm("add.rn.f32x2 %0, %1, %2;" : "=l"(r) : "l"(a), "l"(b)); return r;
}
__device__ __forceinline__ void unpack2(u64 v, float& lo, float& hi) {
    asm("mov.b64 {%0,%1}, %2;" : "=f"(lo), "=f"(hi) : "l"(v));
}

// ---------------- dtype sniffing for edge_index ----------------
__global__ void detect_kernel(const unsigned int* __restrict__ idx) {
    __shared__ unsigned int acc[256];
    unsigned int v = 0;
    for (int i = threadIdx.x; i < 2048; i += 256) v |= idx[2 * i + 1];
    acc[threadIdx.x] = v;
    __syncthreads();
    for (int s = 128; s > 0; s >>= 1) {
        if (threadIdx.x < s) acc[threadIdx.x] |= acc[threadIdx.x + s];
        __syncthreads();
    }
    if (threadIdx.x == 0) g_is64 = (acc[0] == 0u) ? 1 : 0;
}

// ---------------- convert edge_index to int32 src/dst arrays ----------------
__global__ void conv_idx_kernel(const void* __restrict__ eidx, int E) {
    int i = blockIdx.x * 256 + threadIdx.x;
    if (i >= E) return;
    if (g_is64) {
        const long long* p = reinterpret_cast<const long long*>(eidx);
        g_src[i] = (int)p[i];
        g_dst[i] = (int)p[(size_t)E + i];
    } else {
        const int* p = reinterpret_cast<const int*>(eidx);
        g_src[i] = p[i];
        g_dst[i] = p[E + i];
    }
}

// ---------------- P/Q precompute: P = x @ W[0:64] + b ; Q = x @ W[64:128] ----------------
// 4 threads per node, each owns 16 output columns. blockIdx.y: 0 -> P, 1 -> Q.
// half==0 threads also zero g_agg for their node (ordered before edge_kernel).
__global__ void __launch_bounds__(256) pq_kernel(const float* __restrict__ xin,
                                                 const float* __restrict__ msg_w,
                                                 const float* __restrict__ msg_b,
                                                 int l, int N) {
    __shared__ __align__(16) float ws[64 * D];   // 16 KB
    __shared__ __align__(16) float bs[D];
    const int half = blockIdx.y;
    const float* x_src = xin ? xin : g_x;
    const float* W = msg_w + (size_t)l * MSG_IN * D + (size_t)half * 64 * D;
    for (int i = threadIdx.x; i < 64 * D; i += 256) ws[i] = W[i];
    if (threadIdx.x < D) bs[threadIdx.x] = half ? 0.f : msg_b[l * D + threadIdx.x];
    __syncthreads();

    const int t = threadIdx.x;
    const int v = blockIdx.x * 64 + (t >> 2);
    if (v >= N) return;
    const int c0 = (t & 3) * 16;

    if (half == 0) {
        float4 z = make_float4(0.f, 0.f, 0.f, 0.f);
        float4* ap = reinterpret_cast<float4*>(g_agg + (size_t)v * D + c0);
        ap[0] = z; ap[1] = z; ap[2] = z; ap[3] = z;
    }

    u64 acc[8];
    const u64* bp = reinterpret_cast<const u64*>(bs + c0);
#pragma unroll
    for (int j = 0; j < 8; j++) acc[j] = bp[j];

    const float4* xr = reinterpret_cast<const float4*>(x_src + (size_t)v * D);
#pragma unroll 4
    for (int k4 = 0; k4 < 16; k4++) {
        float4 xv = xr[k4];
#pragma unroll
        for (int c = 0; c < 4; c++) {
            float xs = (c == 0) ? xv.x : (c == 1) ? xv.y : (c == 2) ? xv.z : xv.w;
            u64 a = pack2(xs, xs);
            const ulonglong2* wr = reinterpret_cast<const ulonglong2*>(&ws[(k4 * 4 + c) * D + c0]);
#pragma unroll
            for (int j4 = 0; j4 < 4; j4++) {
                ulonglong2 w = wr[j4];
                fma2(acc[2 * j4],     a, w.x);
                fma2(acc[2 * j4 + 1], a, w.y);
            }
        }
    }
    u64* o = reinterpret_cast<u64*>(((half) ? g_Q : g_P) + (size_t)v * D + c0);
#pragma unroll
    for (int j = 0; j < 8; j++) o[j] = acc[j];
}

// ---------------- edge pass: agg[dst] += relu(P[dst] + Q[src] + ea @ W_e) ----------------
// 4 threads/edge, 16 cols each. Gathers issued BEFORE the FMA loop; combine placed
// mid-loop so the ~250-550cyc load latency hides behind ~400cyc of FMA/LDS work.
__global__ void __launch_bounds__(256) edge_kernel(const float* __restrict__ eattr,
                                                   const float* __restrict__ msg_w,
                                                   int l, int E) {
    __shared__ __align__(16) float we[EDGE_DIM * D];   // 4 KB
    const float* W = msg_w + (size_t)l * MSG_IN * D + (size_t)128 * D;
    for (int i = threadIdx.x; i < EDGE_DIM * D; i += 256) we[i] = W[i];
    __syncthreads();

    const int t = threadIdx.x;
    const int e = blockIdx.x * 64 + (t >> 2);
    if (e >= E) return;
    const int c0 = (t & 3) * 16;

    const int src = g_src[e];
    const int dst = g_dst[e];

    // issue gathers up front
    ulonglong2 pv[4], qv[4];
    const ulonglong2* Pp = reinterpret_cast<const ulonglong2*>(g_P + (size_t)dst * D + c0);
    const ulonglong2* Qp = reinterpret_cast<const ulonglong2*>(g_Q + (size_t)src * D + c0);
#pragma unroll
    for (int j = 0; j < 4; j++) { pv[j] = Pp[j]; qv[j] = Qp[j]; }

    float eav[16];
    {
        const float4* ep = reinterpret_cast<const float4*>(eattr + (size_t)e * EDGE_DIM);
        *reinterpret_cast<float4*>(&eav[0])  = ep[0];
        *reinterpret_cast<float4*>(&eav[4])  = ep[1];
        *reinterpret_cast<float4*>(&eav[8])  = ep[2];
        *reinterpret_cast<float4*>(&eav[12]) = ep[3];
    }

    u64 acc[8];
#pragma unroll
    for (int j = 0; j < 8; j++) acc[j] = 0ULL;

    // first half of k while gathers are in flight
#pragma unroll
    for (int k = 0; k < 8; k++) {
        u64 a = pack2(eav[k], eav[k]);
        const ulonglong2* wr = reinterpret_cast<const ulonglong2*>(&we[k * D + c0]);
#pragma unroll
        for (int j4 = 0; j4 < 4; j4++) {
            ulonglong2 w = wr[j4];
            fma2(acc[2 * j4],     a, w.x);
            fma2(acc[2 * j4 + 1], a, w.y);
        }
    }

    // combine P+Q (loads should have returned by now)
    u64 pq[8];
#pragma unroll
    for (int j = 0; j < 4; j++) {
        pq[2 * j]     = add2(pv[j].x, qv[j].x);
        pq[2 * j + 1] = add2(pv[j].y, qv[j].y);
    }

    // second half of k
#pragma unroll
    for (int k = 8; k < 16; k++) {
        u64 a = pack2(eav[k], eav[k]);
        const ulonglong2* wr = reinterpret_cast<const ulonglong2*>(&we[k * D + c0]);
#pragma unroll
        for (int j4 = 0; j4 < 4; j4++) {
            ulonglong2 w = wr[j4];
            fma2(acc[2 * j4],     a, w.x);
            fma2(acc[2 * j4 + 1], a, w.y);
        }
    }

    float* ag = g_agg + (size_t)dst * D + c0;
#pragma unroll
    for (int j = 0; j < 4; j++) {
        u64 s0 = add2(acc[2 * j],     pq[2 * j]);
        u64 s1 = add2(acc[2 * j + 1], pq[2 * j + 1]);
        float a0, a1, a2, a3;
        unpack2(s0, a0, a1);
        unpack2(s1, a2, a3);
        a0 = fmaxf(a0, 0.f); a1 = fmaxf(a1, 0.f);
        a2 = fmaxf(a2, 0.f); a3 = fmaxf(a3, 0.f);
        asm volatile("red.global.add.v4.f32 [%0], {%1,%2,%3,%4};"
                     :: "l"(ag + j * 4), "f"(a0), "f"(a1), "f"(a2), "f"(a3)
                     : "memory");
    }
}

// ---------------- node update: x' = relu([x, agg] @ upd_w + b) ----------------
// 4 threads per node, 16 cols each.
__global__ void __launch_bounds__(256) upd_kernel(const float* __restrict__ xin,
                                                  const float* __restrict__ upd_w,
                                                  const float* __restrict__ upd_b,
                                                  int l, int N, float* __restrict__ xout) {
    __shared__ __align__(16) float ws[UPD_IN * D];   // 32 KB
    __shared__ __align__(16) float bs[D];
    const float* x_src = xin ? xin : g_x;
    float* x_dst = xout ? xout : g_x;
    const float* W = upd_w + (size_t)l * UPD_IN * D;
    for (int i = threadIdx.x; i < UPD_IN * D; i += 256) ws[i] = W[i];
    if (threadIdx.x < D) bs[threadIdx.x] = upd_b[l * D + threadIdx.x];
    __syncthreads();

    const int t = threadIdx.x;
    const int v = blockIdx.x * 64 + (t >> 2);
    if (v >= N) return;
    const int c0 = (t & 3) * 16;

    u64 acc[8];
    const u64* bp = reinterpret_cast<const u64*>(bs + c0);
#pragma unroll
    for (int j = 0; j < 8; j++) acc[j] = bp[j];

    const float4* xr = reinterpret_cast<const float4*>(x_src + (size_t)v * D);
    const float4* ar = reinterpret_cast<const float4*>(g_agg + (size_t)v * D);

#pragma unroll 4
    for (int k4 = 0; k4 < 16; k4++) {
        float4 xv = xr[k4];
#pragma unroll
        for (int c = 0; c < 4; c++) {
            float xs = (c == 0) ? xv.x : (c == 1) ? xv.y : (c == 2) ? xv.z : xv.w;
            u64 a = pack2(xs, xs);
            const ulonglong2* wr = reinterpret_cast<const ulonglong2*>(&ws[(k4 * 4 + c) * D + c0]);
#pragma unroll
            for (int j4 = 0; j4 < 4; j4++) {
                ulonglong2 w = wr[j4];
                fma2(acc[2 * j4],     a, w.x);
                fma2(acc[2 * j4 + 1], a, w.y);
            }
        }
    }
#pragma unroll 4
    for (int k4 = 0; k4 < 16; k4++) {
        float4 av = ar[k4];
#pragma unroll
        for (int c = 0; c < 4; c++) {
            float xs = (c == 0) ? av.x : (c == 1) ? av.y : (c == 2) ? av.z : av.w;
            u64 a = pack2(xs, xs);
            const ulonglong2* wr = reinterpret_cast<const ulonglong2*>(&ws[(64 + k4 * 4 + c) * D + c0]);
#pragma unroll
            for (int j4 = 0; j4 < 4; j4++) {
                ulonglong2 w = wr[j4];
                fma2(acc[2 * j4],     a, w.x);
                fma2(acc[2 * j4 + 1], a, w.y);
            }
        }
    }

    float* o = x_dst + (size_t)v * D + c0;
#pragma unroll
    for (int j = 0; j < 8; j++) {
        float lo, hi;
        unpack2(acc[j], lo, hi);
        float2 rv;
        rv.x = fmaxf(lo, 0.f);
        rv.y = fmaxf(hi, 0.f);
        *reinterpret_cast<float2*>(&o[2 * j]) = rv;
    }
}

// ---------------- launcher ----------------
extern "C" void kernel_launch(void* const* d_in, const int* in_sizes, int n_in,
                              void* d_out, int out_size) {
    const float* x      = (const float*)d_in[0];
    const void*  eidx   = d_in[1];
    const float* eattr  = (const float*)d_in[2];
    const float* msg_w  = (const float*)d_in[3];
    const float* msg_b  = (const float*)d_in[4];
    const float* upd_w  = (const float*)d_in[5];
    const float* upd_b  = (const float*)d_in[6];

    const int N = in_sizes[0] / D;
    const int E = in_sizes[2] / EDGE_DIM;
    const int L = in_sizes[4] / D;

    detect_kernel<<<1, 256>>>((const unsigned int*)eidx);
    conv_idx_kernel<<<(E + 255) / 256, 256>>>(eidx, E);

    const int node_blocks = (N + 63) / 64;     // 4 threads per node
    const int edge_blocks = (E + 63) / 64;     // 4 threads per edge

    for (int l = 0; l < L; l++) {
        const float* xin = (l == 0) ? x : nullptr;            // nullptr -> g_x
        float* xout = (l == L - 1) ? (float*)d_out : nullptr; // nullptr -> g_x

        dim3 pq_grid(node_blocks, 2);
        pq_kernel<<<pq_grid, 256>>>(xin, msg_w, msg_b, l, N);
        edge_kernel<<<edge_blocks, 256>>>(eattr, msg_w, l, E);
        upd_kernel<<<node_blocks, 256>>>(xin, upd_w, upd_b, l, N, xout);
    }
}

// round 6
// speedup vs baseline: 2.0177x; 2.0177x over previous
#include <cuda_runtime.h>
#include <cstdint>

#define D         64
#define EDGE_DIM  16
#define MSG_IN    144
#define UPD_IN    128
#define MAXN      50000
#define MAXE      800000

// ---------------- scratch (device globals; no allocation allowed) ----------------
__device__ __align__(256) float g_x[MAXN * D];
__device__ __align__(256) float g_P[MAXN * D];   // x @ W_i + msg_b  (dst side)
__device__ __align__(256) float g_Q[MAXN * D];   // x @ W_j          (src side)
__device__ __align__(256) float g_agg[MAXN * D];
__device__ int g_src[MAXE];
__device__ int g_dst[MAXE];
__device__ int g_is64;

typedef unsigned long long u64;

// ---------------- packed f32x2 helpers ----------------
__device__ __forceinline__ u64 pack2(float lo, float hi) {
    u64 r; asm("mov.b64 %0, {%1,%2};" : "=l"(r) : "f"(lo), "f"(hi)); return r;
}
__device__ __forceinline__ void fma2(u64& acc, u64 a, u64 b) {
    asm("fma.rn.f32x2 %0, %1, %2, %0;" : "+l"(acc) : "l"(a), "l"(b));
}
__device__ __forceinline__ u64 add2(u64 a, u64 b) {
    u64 r; asm("add.rn.f32x2 %0, %1, %2;" : "=l"(r) : "l"(a), "l"(b)); return r;
}
__device__ __forceinline__ void unpack2(u64 v, float& lo, float& hi) {
    asm("mov.b64 {%0,%1}, %2;" : "=f"(lo), "=f"(hi) : "l"(v));
}

// ---------------- dtype sniffing for edge_index ----------------
__global__ void detect_kernel(const unsigned int* __restrict__ idx) {
    __shared__ unsigned int acc[256];
    unsigned int v = 0;
    for (int i = threadIdx.x; i < 2048; i += 256) v |= idx[2 * i + 1];
    acc[threadIdx.x] = v;
    __syncthreads();
    for (int s = 128; s > 0; s >>= 1) {
        if (threadIdx.x < s) acc[threadIdx.x] |= acc[threadIdx.x + s];
        __syncthreads();
    }
    if (threadIdx.x == 0) g_is64 = (acc[0] == 0u) ? 1 : 0;
}

// ---------------- convert edge_index to int32 src/dst arrays ----------------
__global__ void conv_idx_kernel(const void* __restrict__ eidx, int E) {
    int i = blockIdx.x * 256 + threadIdx.x;
    if (i >= E) return;
    if (g_is64) {
        const long long* p = reinterpret_cast<const long long*>(eidx);
        g_src[i] = (int)p[i];
        g_dst[i] = (int)p[(size_t)E + i];
    } else {
        const int* p = reinterpret_cast<const int*>(eidx);
        g_src[i] = p[i];
        g_dst[i] = p[E + i];
    }
}

// ---------------- zero the aggregation buffer ----------------
__global__ void zero_agg_kernel(int n4) {
    int i = blockIdx.x * blockDim.x + threadIdx.x;
    if (i < n4) reinterpret_cast<float4*>(g_agg)[i] = make_float4(0.f, 0.f, 0.f, 0.f);
}

// ---------------- P/Q precompute (1 thread/node, 64 accumulators) ----------------
__global__ void pq_kernel(const float* __restrict__ xin,
                          const float* __restrict__ msg_w,
                          const float* __restrict__ msg_b,
                          int l, int N) {
    __shared__ __align__(16) float ws[64 * D];   // 16 KB
    __shared__ __align__(16) float bs[D];
    const int half = blockIdx.y;
    const float* x_src = xin ? xin : g_x;
    const float* W = msg_w + (size_t)l * MSG_IN * D + (size_t)half * 64 * D;
    for (int i = threadIdx.x; i < 64 * D; i += 256) ws[i] = W[i];
    if (threadIdx.x < D) bs[threadIdx.x] = half ? 0.f : msg_b[l * D + threadIdx.x];
    __syncthreads();

    int v = blockIdx.x * 256 + threadIdx.x;
    if (v >= N) return;

    u64 acc[32];
    const u64* bp = reinterpret_cast<const u64*>(bs);
#pragma unroll
    for (int j = 0; j < 32; j++) acc[j] = bp[j];

    const float4* xr = reinterpret_cast<const float4*>(x_src + (size_t)v * D);
    for (int k4 = 0; k4 < 16; k4++) {
        float4 xv = xr[k4];
#pragma unroll
        for (int c = 0; c < 4; c++) {
            float xs = (c == 0) ? xv.x : (c == 1) ? xv.y : (c == 2) ? xv.z : xv.w;
            u64 a = pack2(xs, xs);
            const ulonglong2* wr = reinterpret_cast<const ulonglong2*>(&ws[(k4 * 4 + c) * D]);
#pragma unroll
            for (int j4 = 0; j4 < 16; j4++) {
                ulonglong2 w = wr[j4];
                fma2(acc[2 * j4],     a, w.x);
                fma2(acc[2 * j4 + 1], a, w.y);
            }
        }
    }
    float* out = (half ? g_Q : g_P) + (size_t)v * D;
    u64* o64 = reinterpret_cast<u64*>(out);
#pragma unroll
    for (int j = 0; j < 32; j++) o64[j] = acc[j];
}

// ---------------- edge pass: warp-per-edge, W_e in registers, shfl-broadcast eattr ----------------
// agg[dst] += relu(P[dst] + Q[src] + ea @ W_e). Lane owns cols (2*lane, 2*lane+1).
#define EPW 16  // edges per warp
__global__ void __launch_bounds__(256) edge_kernel(const float* __restrict__ eattr,
                                                   const float* __restrict__ msg_w,
                                                   int l, int E) {
    const float* W = msg_w + (size_t)l * MSG_IN * D + (size_t)128 * D;
    const int lane = threadIdx.x & 31;
    const int gwarp = (blockIdx.x * 256 + threadIdx.x) >> 5;

    // W_e column pair for this lane: 16 u64 registers, loaded once per warp.
    u64 Wreg[16];
#pragma unroll
    for (int k = 0; k < 16; k++)
        Wreg[k] = *reinterpret_cast<const u64*>(W + k * D + 2 * lane);

    const int e0 = gwarp * EPW;
#pragma unroll 2
    for (int i = 0; i < EPW; i++) {
        const int e = e0 + i;
        if (e < E) {
            const int src = g_src[e];
            const int dst = g_dst[e];
            float myea = 0.f;
            if (lane < EDGE_DIM) myea = eattr[(size_t)e * EDGE_DIM + lane];

            const u64 p = *reinterpret_cast<const u64*>(g_P + (size_t)dst * D + 2 * lane);
            const u64 q = *reinterpret_cast<const u64*>(g_Q + (size_t)src * D + 2 * lane);

            u64 acc0 = add2(p, q);
            u64 acc1 = 0ULL;
#pragma unroll
            for (int k = 0; k < EDGE_DIM; k += 2) {
                float s0 = __shfl_sync(0xffffffffu, myea, k);
                float s1 = __shfl_sync(0xffffffffu, myea, k + 1);
                fma2(acc0, pack2(s0, s0), Wreg[k]);
                fma2(acc1, pack2(s1, s1), Wreg[k + 1]);
            }
            acc0 = add2(acc0, acc1);

            float lo, hi;
            unpack2(acc0, lo, hi);
            lo = fmaxf(lo, 0.f);
            hi = fmaxf(hi, 0.f);
            asm volatile("red.global.add.v2.f32 [%0], {%1,%2};"
                         :: "l"(g_agg + (size_t)dst * D + 2 * lane), "f"(lo), "f"(hi)
                         : "memory");
        }
    }
}

// ---------------- node update (1 thread/node) ----------------
__global__ void upd_kernel(const float* __restrict__ xin,
                           const float* __restrict__ upd_w,
                           const float* __restrict__ upd_b,
                           int l, int N, float* __restrict__ xout) {
    __shared__ __align__(16) float ws[UPD_IN * D];   // 32 KB
    __shared__ __align__(16) float bs[D];
    const float* x_src = xin ? xin : g_x;
    float* x_dst = xout ? xout : g_x;
    const float* W = upd_w + (size_t)l * UPD_IN * D;
    for (int i = threadIdx.x; i < UPD_IN * D; i += 256) ws[i] = W[i];
    if (threadIdx.x < D) bs[threadIdx.x] = upd_b[l * D + threadIdx.x];
    __syncthreads();

    int v = blockIdx.x * 256 + threadIdx.x;
    if (v >= N) return;

    u64 acc[32];
    const u64* bp = reinterpret_cast<const u64*>(bs);
#pragma unroll
    for (int j = 0; j < 32; j++) acc[j] = bp[j];

    const float4* xr = reinterpret_cast<const float4*>(x_src + (size_t)v * D);
    const float4* ar = reinterpret_cast<const float4*>(g_agg + (size_t)v * D);

    for (int k4 = 0; k4 < 16; k4++) {
        float4 xv = xr[k4];
#pragma unroll
        for (int c = 0; c < 4; c++) {
            float xs = (c == 0) ? xv.x : (c == 1) ? xv.y : (c == 2) ? xv.z : xv.w;
            u64 a = pack2(xs, xs);
            const ulonglong2* wr = reinterpret_cast<const ulonglong2*>(&ws[(k4 * 4 + c) * D]);
#pragma unroll
            for (int j4 = 0; j4 < 16; j4++) {
                ulonglong2 w = wr[j4];
                fma2(acc[2 * j4],     a, w.x);
                fma2(acc[2 * j4 + 1], a, w.y);
            }
        }
    }
    for (int k4 = 0; k4 < 16; k4++) {
        float4 av = ar[k4];
#pragma unroll
        for (int c = 0; c < 4; c++) {
            float xs = (c == 0) ? av.x : (c == 1) ? av.y : (c == 2) ? av.z : av.w;
            u64 a = pack2(xs, xs);
            const ulonglong2* wr = reinterpret_cast<const ulonglong2*>(&ws[(64 + k4 * 4 + c) * D]);
#pragma unroll
            for (int j4 = 0; j4 < 16; j4++) {
                ulonglong2 w = wr[j4];
                fma2(acc[2 * j4],     a, w.x);
                fma2(acc[2 * j4 + 1], a, w.y);
            }
        }
    }

    float* o = x_dst + (size_t)v * D;
#pragma unroll
    for (int j = 0; j < 32; j++) {
        float lo, hi;
        unpack2(acc[j], lo, hi);
        float2 rv;
        rv.x = fmaxf(lo, 0.f);
        rv.y = fmaxf(hi, 0.f);
        *reinterpret_cast<float2*>(&o[2 * j]) = rv;
    }
}

// ---------------- launcher ----------------
extern "C" void kernel_launch(void* const* d_in, const int* in_sizes, int n_in,
                              void* d_out, int out_size) {
    const float* x      = (const float*)d_in[0];
    const void*  eidx   = d_in[1];
    const float* eattr  = (const float*)d_in[2];
    const float* msg_w  = (const float*)d_in[3];
    const float* msg_b  = (const float*)d_in[4];
    const float* upd_w  = (const float*)d_in[5];
    const float* upd_b  = (const float*)d_in[6];

    const int N = in_sizes[0] / D;
    const int E = in_sizes[2] / EDGE_DIM;
    const int L = in_sizes[4] / D;

    detect_kernel<<<1, 256>>>((const unsigned int*)eidx);
    conv_idx_kernel<<<(E + 255) / 256, 256>>>(eidx, E);

    const int node_blocks = (N + 255) / 256;               // 1 thread per node
    const int zero_blocks = ((N * D / 4) + 255) / 256;
    // edges per block = (256/32) warps * EPW edges = 8*EPW
    const int edge_blocks = (E + 8 * EPW - 1) / (8 * EPW);

    for (int l = 0; l < L; l++) {
        const float* xin = (l == 0) ? x : nullptr;            // nullptr -> g_x
        float* xout = (l == L - 1) ? (float*)d_out : nullptr; // nullptr -> g_x

        dim3 pq_grid(node_blocks, 2);
        pq_kernel<<<pq_grid, 256>>>(xin, msg_w, msg_b, l, N);
        zero_agg_kernel<<<zero_blocks, 256>>>(N * D / 4);
        edge_kernel<<<edge_blocks, 256>>>(eattr, msg_w, l, E);
        upd_kernel<<<node_blocks, 256>>>(xin, upd_w, upd_b, l, N, xout);
    }
}